// round 5
// baseline (speedup 1.0000x reference)
#include <cuda_runtime.h>
#include <math.h>

// ---------------------------------------------------------------------------
// out[k] = sigmoid( concat(feature[a], feature[b]) @ W1 @ W2 @ W3 @ W4 + c )
// Collapsed affine form:
//   v4 = W4[:,0] (64), v3 = W3 v4 (512), v2 = W2 v3 (1024), v1 = W1 v2 (1802)
//   c  = b1.v2 + b2.v3 + b3.v4 + b4[0]
//   s1[e] = feature[e] . v1[0:901], s2[e] = feature[e] . v1[901:1802]
//   out[k] = sigmoid(s1[a] + s2[b] + c)
//
// k_scores streams feature (72 MB) with aligned float4s. Row r spans exactly
// 226 aligned float4s (900 % 4 == 0). v1 is replicated into 4 shift tables
// T[sh][q] = v1[4q-sh .. 4q-sh+3] (zero-padded at borders), which k_scores
// caches in SHARED memory so the global path carries only the feature stream.
// ---------------------------------------------------------------------------

#define N_ENT 20000
#define D     901
#define B_TR  100000
#define B_TE  25000
#define TQ    228     // table entries per shift (q in [0,226), padded)

__device__ __align__(16) float g_v3[512];
__device__ __align__(16) float g_v2[1024];
__device__ float g_c;
__device__ __align__(16) float4 g_T1[4][TQ];   // first half  of v1 (cols 0..900)
__device__ __align__(16) float4 g_T2[4][TQ];   // second half of v1
__device__ __align__(16) float g_s[2 * N_ENT]; // s1[e]=g_s[2e], s2[e]=g_s[2e+1]

// ---- fused: v3 = W3 @ W4col (redundant per block, coalesced warp-per-row),
//      then v2 = W2 @ v3 ----
__global__ void __launch_bounds__(256) k_v23(const float* __restrict__ W3,
                                             const float* __restrict__ W4,
                                             const float* __restrict__ W2) {
    __shared__ float s_v3[512];
    __shared__ float s_w4[64];
    int t = threadIdx.x;
    int warp = t >> 5, lane = t & 31;
    if (t < 64) s_w4[t] = __ldg(W4 + t);
    __syncthreads();
    float w4a = s_w4[lane], w4b = s_w4[lane + 32];
    for (int r = warp; r < 512; r += 8) {
        const float* row = W3 + r * 64;
        float a = fmaf(__ldg(row + lane), w4a, __ldg(row + lane + 32) * w4b);
        #pragma unroll
        for (int o = 16; o; o >>= 1) a += __shfl_down_sync(0xffffffffu, a, o);
        if (lane == 0) s_v3[r] = a;
    }
    __syncthreads();

    int r = blockIdx.x * 8 + warp;                 // 128 blocks * 8 warps = 1024 rows
    const float4* row = (const float4*)W2 + (size_t)r * 128;
    const float4* v   = (const float4*)s_v3;
    float acc = 0.f;
    #pragma unroll
    for (int i = 0; i < 4; i++) {
        int j = lane + 32 * i;
        float4 a4 = __ldg(row + j);
        float4 b4 = v[j];
        acc = fmaf(a4.x, b4.x, acc);
        acc = fmaf(a4.y, b4.y, acc);
        acc = fmaf(a4.z, b4.z, acc);
        acc = fmaf(a4.w, b4.w, acc);
    }
    #pragma unroll
    for (int o = 16; o; o >>= 1) acc += __shfl_down_sync(0xffffffffu, acc, o);
    if (lane == 0) g_v2[r] = acc;

    if (blockIdx.x == 0) {                          // publish v3 for the bias kernel
        __syncthreads();
        for (int rr = t; rr < 512; rr += 256) g_v3[rr] = s_v3[rr];
    }
}

// ---- v1 = W1 @ v2 (1802 warp-rows), results scattered into shift tables.
//      Last block computes c = b1.v2 + b2.v3 + b3.v4 + b4. ----
__global__ void __launch_bounds__(256) k_v1_bias(const float* __restrict__ W1,
                          const float* __restrict__ b1, const float* __restrict__ b2,
                          const float* __restrict__ b3, const float* __restrict__ b4,
                          const float* __restrict__ W4) {
    if (blockIdx.x == gridDim.x - 1) {
        __shared__ float red[8];
        int t = threadIdx.x;
        float acc = 0.f;
        #pragma unroll
        for (int j = t; j < 1024; j += 256) acc = fmaf(__ldg(b1 + j), g_v2[j], acc);
        #pragma unroll
        for (int j = t; j < 512; j += 256)  acc = fmaf(__ldg(b2 + j), g_v3[j], acc);
        if (t < 64)                         acc = fmaf(__ldg(b3 + t), __ldg(W4 + t), acc);
        #pragma unroll
        for (int o = 16; o; o >>= 1) acc += __shfl_down_sync(0xffffffffu, acc, o);
        if ((t & 31) == 0) red[t >> 5] = acc;
        __syncthreads();
        if (t == 0) {
            float s = __ldg(b4);
            #pragma unroll
            for (int w = 0; w < 8; w++) s += red[w];
            g_c = s;
        }
        return;
    }
    int warp = (blockIdx.x * blockDim.x + threadIdx.x) >> 5;
    int lane = threadIdx.x & 31;
    if (warp >= 2 * D) return;
    const float4* row = (const float4*)W1 + (size_t)warp * 256;  // 1024/4
    const float4* v4  = (const float4*)g_v2;
    float acc = 0.f;
    #pragma unroll
    for (int i = 0; i < 8; i++) {
        int j = lane + 32 * i;
        float4 a = __ldg(row + j);
        float4 b = v4[j];
        acc = fmaf(a.x, b.x, acc);
        acc = fmaf(a.y, b.y, acc);
        acc = fmaf(a.z, b.z, acc);
        acc = fmaf(a.w, b.w, acc);
    }
    #pragma unroll
    for (int o = 16; o; o >>= 1) acc += __shfl_down_sync(0xffffffffu, acc, o);
    if (lane == 0) {
        int   col = (warp < D) ? warp : warp - D;
        float* Tb = (warp < D) ? (float*)g_T1 : (float*)g_T2;
        #pragma unroll
        for (int sh = 0; sh < 4; sh++) {
            int idx = col + sh;                 // element slot: T[sh][idx>>2][idx&3]
            Tb[sh * (4 * TQ) + idx] = acc;
        }
    }
}

// ---- per-entity scores: warp-per-row float4 streaming, tables in SMEM ----
__global__ void __launch_bounds__(256) k_scores(const float4* __restrict__ feat4) {
    __shared__ float4 sT1[4 * TQ];
    __shared__ float4 sT2[4 * TQ];
    int t = threadIdx.x;
    const float4* gT1 = (const float4*)g_T1;
    const float4* gT2 = (const float4*)g_T2;
    #pragma unroll
    for (int i = t; i < 4 * TQ; i += 256) {
        sT1[i] = gT1[i];
        sT2[i] = gT2[i];
    }
    __syncthreads();

    int warp = (blockIdx.x * blockDim.x + t) >> 5;
    int lane = t & 31;
    if (warp >= N_ENT) return;
    int s  = warp * D;
    int f0 = s >> 2;
    int sh = s & 3;
    const float4* T1 = sT1 + sh * TQ;
    const float4* T2 = sT2 + sh * TQ;
    float s1 = 0.f, s2 = 0.f;
    #pragma unroll
    for (int i = 0; i < 7; i++) {              // q = 0..223, all lanes active
        int q = lane + 32 * i;
        float4 f = __ldcs(feat4 + f0 + q);     // streaming: evict-first
        float4 a = T1[q];
        float4 b = T2[q];
        s1 = fmaf(f.x, a.x, s1); s1 = fmaf(f.y, a.y, s1);
        s1 = fmaf(f.z, a.z, s1); s1 = fmaf(f.w, a.w, s1);
        s2 = fmaf(f.x, b.x, s2); s2 = fmaf(f.y, b.y, s2);
        s2 = fmaf(f.z, b.z, s2); s2 = fmaf(f.w, b.w, s2);
    }
    if (lane < 2) {                            // q = 224, 225 (226 total)
        int q = 224 + lane;
        float4 f = __ldcs(feat4 + f0 + q);
        float4 a = T1[q];
        float4 b = T2[q];
        s1 = fmaf(f.x, a.x, s1); s1 = fmaf(f.y, a.y, s1);
        s1 = fmaf(f.z, a.z, s1); s1 = fmaf(f.w, a.w, s1);
        s2 = fmaf(f.x, b.x, s2); s2 = fmaf(f.y, b.y, s2);
        s2 = fmaf(f.z, b.z, s2); s2 = fmaf(f.w, b.w, s2);
    }
    #pragma unroll
    for (int o = 16; o; o >>= 1) {
        s1 += __shfl_down_sync(0xffffffffu, s1, o);
        s2 += __shfl_down_sync(0xffffffffu, s2, o);
    }
    if (lane == 0) {
        g_s[2 * warp]     = s1;
        g_s[2 * warp + 1] = s2;
    }
}

// ---- gather + sigmoid: 2 pairs per thread (int4 pair loads, float2 stores) ----
// train pairs first (100000 -> 50000 threads), then test (25000 -> 12500).
__global__ void __launch_bounds__(256) k_out(const int4* __restrict__ tr4,
                                             const int4* __restrict__ te4,
                                             float2* __restrict__ out2) {
    int k = blockIdx.x * blockDim.x + threadIdx.x;
    const int NT = B_TR / 2, NE = B_TE / 2;      // 50000, 12500
    if (k >= NT + NE) return;
    int4 p = (k < NT) ? __ldg(tr4 + k) : __ldg(te4 + (k - NT));
    // 4 independent gathers
    float a0 = g_s[2 * p.x], b0 = g_s[2 * p.y + 1];
    float a1 = g_s[2 * p.z], b1 = g_s[2 * p.w + 1];
    float c = g_c;
    float z0 = a0 + b0 + c;
    float z1 = a1 + b1 + c;
    float2 o;
    o.x = 1.0f / (1.0f + __expf(-z0));
    o.y = 1.0f / (1.0f + __expf(-z1));
    out2[k] = o;
}

extern "C" void kernel_launch(void* const* d_in, const int* in_sizes, int n_in,
                              void* d_out, int out_size) {
    const float* feature = (const float*)d_in[0];   // [20000, 901]
    const float* W1      = (const float*)d_in[1];   // [1802, 1024]
    const float* b1      = (const float*)d_in[2];   // [1024]
    const float* W2      = (const float*)d_in[3];   // [1024, 512]
    const float* b2      = (const float*)d_in[4];   // [512]
    const float* W3      = (const float*)d_in[5];   // [512, 64]
    const float* b3      = (const float*)d_in[6];   // [64]
    const float* W4      = (const float*)d_in[7];   // [64, 1]
    const float* b4      = (const float*)d_in[8];   // [1]
    const int4*  tr4     = (const int4*)d_in[9];    // [100000, 2] -> 50000 int4
    const int4*  te4     = (const int4*)d_in[10];   // [25000, 2]  -> 12500 int4
    float2*      out2    = (float2*)d_out;

    // v3 + v2 (fused), 128 blocks x 8 warps = 1024 rows
    k_v23<<<128, 256>>>(W3, W4, W2);
    // v1 -> shift tables (+ bias constant in last block): 1802 rows / 8 + 1
    k_v1_bias<<<(2 * D + 7) / 8 + 1, 256>>>(W1, b1, b2, b3, b4, W4);
    // per-entity scores: 20000 warps, tables cached in smem
    k_scores<<<(N_ENT + 7) / 8, 256>>>((const float4*)feature);
    // final gather + sigmoid: 62500 threads
    k_out<<<(62500 + 255) / 256, 256>>>(tr4, te4, out2);
}

// round 6
// speedup vs baseline: 1.6953x; 1.6953x over previous
#include <cuda_runtime.h>
#include <math.h>
#include <stdint.h>

// ---------------------------------------------------------------------------
// out[k] = sigmoid( concat(feature[a], feature[b]) @ W1 @ W2 @ W3 @ W4 + c )
// Collapsed affine form (no inter-layer activations):
//   v4 = W4[:,0] (64), v3 = W3 v4 (512), v2 = W2 v3 (1024), v1 = W1 v2 (1802)
//   c  = b1.v2 + b2.v3 + b3.v4 + b4[0]
//   s1[e] = feature[e] . v1[0:901], s2[e] = feature[e] . v1[901:1802]
//   out[k] = sigmoid(s1[a] + s2[b] + c)
//
// k_scores streams feature (72 MB) via cp.async.bulk into a 3-stage smem ring
// (8 rows / 28832 B per tile). Producer warp issues bulk copies; 8 consumer
// warps dot-product one row each with v1 weights held in REGISTERS.
// ---------------------------------------------------------------------------

#define N_ENT 20000
#define D     901
#define B_TR  100000
#define B_TE  25000

#define TILE_ROWS  8
#define TILE_BYTES (TILE_ROWS * D * 4)     // 28832, multiple of 16
#define N_TILES    (N_ENT / TILE_ROWS)     // 2500
#define SC_GRID    296
#define SC_THREADS 288                     // 8 consumer warps + 1 producer warp
#define SC_SMEM    (64 + 3 * TILE_BYTES)   // 86560 bytes

__device__ __align__(16) float g_v3[512];
__device__ __align__(16) float g_v2[1024];
__device__ __align__(16) float g_v1[2 * D];    // collapsed weight vector
__device__ float g_c;
__device__ __align__(16) float g_s[2 * N_ENT]; // s1[e]=g_s[2e], s2[e]=g_s[2e+1]

// ---- mbarrier / bulk-copy primitives ----
__device__ __forceinline__ void mbar_init(uint32_t addr, uint32_t count) {
    asm volatile("mbarrier.init.shared.b64 [%0], %1;" :: "r"(addr), "r"(count) : "memory");
}
__device__ __forceinline__ void mbar_expect_tx(uint32_t addr, uint32_t bytes) {
    asm volatile("mbarrier.arrive.expect_tx.shared.b64 _, [%0], %1;"
                 :: "r"(addr), "r"(bytes) : "memory");
}
__device__ __forceinline__ void mbar_arrive(uint32_t addr) {
    asm volatile("mbarrier.arrive.shared.b64 _, [%0];" :: "r"(addr) : "memory");
}
__device__ __forceinline__ void mbar_wait(uint32_t addr, uint32_t parity) {
    asm volatile(
        "{\n\t.reg .pred P;\n\t"
        "WAIT_%=:\n\t"
        "mbarrier.try_wait.parity.acquire.cta.shared::cta.b64 P, [%0], %1, 0x989680;\n\t"
        "@P bra.uni DONE_%=;\n\t"
        "bra.uni WAIT_%=;\n\t"
        "DONE_%=:\n\t}"
        :: "r"(addr), "r"(parity) : "memory");
}
__device__ __forceinline__ void bulk_g2s(uint32_t dst_smem, const void* src_gmem,
                                         uint32_t bytes, uint32_t mbar) {
    asm volatile(
        "cp.async.bulk.shared::cluster.global.mbarrier::complete_tx::bytes [%0], [%1], %2, [%3];"
        :: "r"(dst_smem), "l"(src_gmem), "r"(bytes), "r"(mbar) : "memory");
}

// ---- fused: v3 = W3 @ W4col (coalesced warp-per-row, per-block redundant),
//      then v2 = W2 @ v3 ----
__global__ void __launch_bounds__(256) k_v23(const float* __restrict__ W3,
                                             const float* __restrict__ W4,
                                             const float* __restrict__ W2) {
    __shared__ float s_v3[512];
    __shared__ float s_w4[64];
    int t = threadIdx.x;
    int warp = t >> 5, lane = t & 31;
    if (t < 64) s_w4[t] = __ldg(W4 + t);
    __syncthreads();
    float w4a = s_w4[lane], w4b = s_w4[lane + 32];
    for (int r = warp; r < 512; r += 8) {
        const float* row = W3 + r * 64;
        float a = fmaf(__ldg(row + lane), w4a, __ldg(row + lane + 32) * w4b);
        #pragma unroll
        for (int o = 16; o; o >>= 1) a += __shfl_down_sync(0xffffffffu, a, o);
        if (lane == 0) s_v3[r] = a;
    }
    __syncthreads();

    int r = blockIdx.x * 8 + warp;                 // 128 blocks * 8 warps = 1024 rows
    const float4* row = (const float4*)W2 + (size_t)r * 128;
    const float4* v   = (const float4*)s_v3;
    float acc = 0.f;
    #pragma unroll
    for (int i = 0; i < 4; i++) {
        int j = lane + 32 * i;
        float4 a4 = __ldg(row + j);
        float4 b4 = v[j];
        acc = fmaf(a4.x, b4.x, acc);
        acc = fmaf(a4.y, b4.y, acc);
        acc = fmaf(a4.z, b4.z, acc);
        acc = fmaf(a4.w, b4.w, acc);
    }
    #pragma unroll
    for (int o = 16; o; o >>= 1) acc += __shfl_down_sync(0xffffffffu, acc, o);
    if (lane == 0) g_v2[r] = acc;

    if (blockIdx.x == 0) {                          // publish v3 for the bias kernel
        __syncthreads();
        for (int rr = t; rr < 512; rr += 256) g_v3[rr] = s_v3[rr];
    }
}

// ---- v1 = W1 @ v2 (1802 warp-rows). Last block computes the bias constant. ----
__global__ void __launch_bounds__(256) k_v1_bias(const float* __restrict__ W1,
                          const float* __restrict__ b1, const float* __restrict__ b2,
                          const float* __restrict__ b3, const float* __restrict__ b4,
                          const float* __restrict__ W4) {
    if (blockIdx.x == gridDim.x - 1) {
        __shared__ float red[8];
        int t = threadIdx.x;
        float acc = 0.f;
        #pragma unroll
        for (int j = t; j < 1024; j += 256) acc = fmaf(__ldg(b1 + j), g_v2[j], acc);
        #pragma unroll
        for (int j = t; j < 512; j += 256)  acc = fmaf(__ldg(b2 + j), g_v3[j], acc);
        if (t < 64)                         acc = fmaf(__ldg(b3 + t), __ldg(W4 + t), acc);
        #pragma unroll
        for (int o = 16; o; o >>= 1) acc += __shfl_down_sync(0xffffffffu, acc, o);
        if ((t & 31) == 0) red[t >> 5] = acc;
        __syncthreads();
        if (t == 0) {
            float s = __ldg(b4);
            #pragma unroll
            for (int w = 0; w < 8; w++) s += red[w];
            g_c = s;
        }
        return;
    }
    int warp = (blockIdx.x * blockDim.x + threadIdx.x) >> 5;
    int lane = threadIdx.x & 31;
    if (warp >= 2 * D) return;
    const float4* row = (const float4*)W1 + (size_t)warp * 256;  // 1024/4
    const float4* v4  = (const float4*)g_v2;
    float acc = 0.f;
    #pragma unroll
    for (int i = 0; i < 8; i++) {
        int j = lane + 32 * i;
        float4 a = __ldg(row + j);
        float4 b = v4[j];
        acc = fmaf(a.x, b.x, acc);
        acc = fmaf(a.y, b.y, acc);
        acc = fmaf(a.z, b.z, acc);
        acc = fmaf(a.w, b.w, acc);
    }
    #pragma unroll
    for (int o = 16; o; o >>= 1) acc += __shfl_down_sync(0xffffffffu, acc, o);
    if (lane == 0) g_v1[warp] = acc;
}

// ---- per-entity scores: cp.async.bulk pipeline, weights in registers ----
__global__ void __launch_bounds__(SC_THREADS) k_scores_tma(const float* __restrict__ feat) {
    extern __shared__ __align__(16) unsigned char smem_raw[];
    uint32_t smem = (uint32_t)__cvta_generic_to_shared(smem_raw);
    float* smemf = (float*)smem_raw;
    const uint32_t mb_full    = smem;        // 3 x 8B at 0,8,16
    const uint32_t mb_empty   = smem + 24;   // 3 x 8B at 24,32,40
    const uint32_t stage_base = smem + 64;

    int tid = threadIdx.x;
    if (tid == 0) {
        #pragma unroll
        for (int s = 0; s < 3; s++) {
            mbar_init(mb_full  + 8u * s, 1);
            mbar_init(mb_empty + 8u * s, 8);
        }
    }
    __syncthreads();

    int b = blockIdx.x;

    if (tid >= 256) {
        // ---- producer warp (single thread issues) ----
        if (tid == 256) {
            int it = 0;
            for (int t = b; t < N_TILES; t += SC_GRID, it++) {
                int s  = it % 3;
                int ph = ((it / 3) & 1) ^ 1;   // first use of each stage passes
                mbar_wait(mb_empty + 8u * s, ph);
                mbar_expect_tx(mb_full + 8u * s, TILE_BYTES);
                bulk_g2s(stage_base + (uint32_t)s * TILE_BYTES,
                         feat + (size_t)t * TILE_ROWS * D,
                         TILE_BYTES, mb_full + 8u * s);
            }
        }
        return;
    }

    // ---- consumer warps: one row per warp per tile ----
    int warp = tid >> 5, lane = tid & 31;
    float rw1[28], rw2[28];
    #pragma unroll
    for (int i = 0; i < 28; i++) {
        rw1[i] = __ldg(g_v1 + lane + 32 * i);
        rw2[i] = __ldg(g_v1 + D + lane + 32 * i);
    }
    float rw1t = 0.f, rw2t = 0.f;
    if (lane < 5) {
        rw1t = __ldg(g_v1 + 896 + lane);
        rw2t = __ldg(g_v1 + D + 896 + lane);
    }

    int it = 0;
    for (int t = b; t < N_TILES; t += SC_GRID, it++) {
        int s  = it % 3;
        int ph = (it / 3) & 1;
        mbar_wait(mb_full + 8u * s, ph);
        int rbase = 16 + s * (TILE_BYTES / 4) + warp * D;   // float index of row start
        float s1 = 0.f, s2 = 0.f;
        #pragma unroll
        for (int i = 0; i < 28; i++) {
            float f = smemf[rbase + lane + 32 * i];
            s1 = fmaf(f, rw1[i], s1);
            s2 = fmaf(f, rw2[i], s2);
        }
        if (lane < 5) {
            float f = smemf[rbase + 896 + lane];
            s1 = fmaf(f, rw1t, s1);
            s2 = fmaf(f, rw2t, s2);
        }
        #pragma unroll
        for (int o = 16; o; o >>= 1) {
            s1 += __shfl_down_sync(0xffffffffu, s1, o);
            s2 += __shfl_down_sync(0xffffffffu, s2, o);
        }
        if (lane == 0) {
            int row = t * TILE_ROWS + warp;
            g_s[2 * row]     = s1;
            g_s[2 * row + 1] = s2;
            mbar_arrive(mb_empty + 8u * s);   // after reduce: all lanes' reads done
        }
    }
}

// ---- gather + sigmoid: train (100000) then test (25000) ----
__global__ void __launch_bounds__(256) k_out(const int2* __restrict__ tr,
                                             const int2* __restrict__ te,
                                             float* __restrict__ out) {
    int k = blockIdx.x * blockDim.x + threadIdx.x;
    if (k >= B_TR + B_TE) return;
    int2 p = (k < B_TR) ? __ldg(tr + k) : __ldg(te + (k - B_TR));
    float z = g_s[2 * p.x] + g_s[2 * p.y + 1] + g_c;
    out[k] = 1.0f / (1.0f + __expf(-z));
}

extern "C" void kernel_launch(void* const* d_in, const int* in_sizes, int n_in,
                              void* d_out, int out_size) {
    const float* feature = (const float*)d_in[0];   // [20000, 901]
    const float* W1      = (const float*)d_in[1];   // [1802, 1024]
    const float* b1      = (const float*)d_in[2];   // [1024]
    const float* W2      = (const float*)d_in[3];   // [1024, 512]
    const float* b2      = (const float*)d_in[4];   // [512]
    const float* W3      = (const float*)d_in[5];   // [512, 64]
    const float* b3      = (const float*)d_in[6];   // [64]
    const float* W4      = (const float*)d_in[7];   // [64, 1]
    const float* b4      = (const float*)d_in[8];   // [1]
    const int2*  tr      = (const int2*)d_in[9];    // [100000, 2]
    const int2*  te      = (const int2*)d_in[10];   // [25000, 2]
    float*       out     = (float*)d_out;

    cudaFuncSetAttribute(k_scores_tma, cudaFuncAttributeMaxDynamicSharedMemorySize, SC_SMEM);

    // v3 + v2 (fused), 128 blocks x 8 warps = 1024 rows
    k_v23<<<128, 256>>>(W3, W4, W2);
    // v1 (1802 rows) + bias constant (last block)
    k_v1_bias<<<(2 * D + 7) / 8 + 1, 256>>>(W1, b1, b2, b3, b4, W4);
    // per-entity scores: bulk-copy pipeline, 296 blocks x 9 warps
    k_scores_tma<<<SC_GRID, SC_THREADS, SC_SMEM>>>(feature);
    // final gather + sigmoid
    k_out<<<(B_TR + B_TE + 255) / 256, 256>>>(tr, te, out);
}